// round 1
// baseline (speedup 1.0000x reference)
#include <cuda_runtime.h>
#include <math.h>

#define N_NODES 50000
#define N_EDGES 1600000
// IN_DIM = 128, HEADS*HIDDEN = 128, OUT_DIM = 64

// ---------------- static device scratch (no allocations allowed) ----------------
__device__ int   g_deg[N_NODES];
__device__ int   g_rs[N_NODES + 1];   // CSR row_start by dst
__device__ int   g_cur[N_NODES];      // fill cursors
__device__ int   g_col[N_EDGES];      // src indices grouped by dst
__device__ float g_feat1[N_NODES * 128];
__device__ float g_h1[N_NODES * 128];
__device__ float g_feat2[N_NODES * 64];

// ---------------- CSR build ----------------
__global__ void k_reset() {
    int i = blockIdx.x * blockDim.x + threadIdx.x;
    if (i < N_NODES) g_deg[i] = 0;
}

__global__ void k_hist(const int* __restrict__ dst) {
    int i = blockIdx.x * blockDim.x + threadIdx.x;
    if (i < N_EDGES) atomicAdd(&g_deg[dst[i]], 1);
}

// single-block exclusive scan over 50000 degrees
__global__ void k_scan() {
    __shared__ int sums[1024];
    const int PER = (N_NODES + 1023) / 1024;  // 49
    int t = threadIdx.x;
    int beg = t * PER;
    int end = min(beg + PER, N_NODES);
    int s = 0;
    for (int i = beg; i < end; i++) s += g_deg[i];
    sums[t] = s;
    __syncthreads();
    for (int off = 1; off < 1024; off <<= 1) {
        int v = (t >= off) ? sums[t - off] : 0;
        __syncthreads();
        sums[t] += v;
        __syncthreads();
    }
    int run = (t == 0) ? 0 : sums[t - 1];
    for (int i = beg; i < end; i++) {
        g_rs[i]  = run;
        g_cur[i] = run;
        run += g_deg[i];
    }
    if (t == 1023) g_rs[N_NODES] = run;
}

__global__ void k_fill(const int* __restrict__ src, const int* __restrict__ dst) {
    int i = blockIdx.x * blockDim.x + threadIdx.x;
    if (i < N_EDGES) {
        int d = dst[i];
        int pos = atomicAdd(&g_cur[d], 1);
        g_col[pos] = src[i];
    }
}

// ---------------- GEMM: Y[N, MOUT] = X[N, 128] @ W[128, MOUT] ----------------
// 256 threads, 64-row tile, 32-col tiles; Xs stored with XOR-ish rotation swizzle
// (element (r,k) at r*128 + ((k + 4r) & 127)) for conflict-free column reads.
template <int MOUT>
__global__ __launch_bounds__(256) void k_gemm(const float* __restrict__ X,
                                              const float* __restrict__ W,
                                              float* __restrict__ Y) {
    __shared__ float Xs[64 * 128];  // 32 KB
    __shared__ float Ws[128 * 32];  // 16 KB  (total = 48 KB static)
    int row0 = blockIdx.x * 64;
    int tid = threadIdx.x;

    for (int idx = tid; idx < 64 * 32; idx += 256) {
        int r = idx >> 5, k4 = idx & 31;
        float4 v = make_float4(0.f, 0.f, 0.f, 0.f);
        int gr = row0 + r;
        if (gr < N_NODES) v = *reinterpret_cast<const float4*>(X + gr * 128 + k4 * 4);
        int co = (k4 * 4 + r * 4) & 127;
        *reinterpret_cast<float4*>(Xs + r * 128 + co) = v;
    }

    int cg = tid & 7;     // 8 column groups of 4
    int rg = tid >> 3;    // 32 row groups of 2
    int r0 = rg * 2, r1 = r0 + 1;
    int sh0 = (r0 * 4) & 127, sh1 = (r1 * 4) & 127;

#pragma unroll
    for (int ct = 0; ct < MOUT; ct += 32) {
        for (int idx = tid; idx < 128 * 8; idx += 256) {
            int k = idx >> 3, c4 = idx & 7;
            *reinterpret_cast<float4*>(Ws + k * 32 + c4 * 4) =
                *reinterpret_cast<const float4*>(W + k * MOUT + ct + c4 * 4);
        }
        __syncthreads();

        float4 a0 = make_float4(0.f, 0.f, 0.f, 0.f);
        float4 a1 = make_float4(0.f, 0.f, 0.f, 0.f);
#pragma unroll 8
        for (int k = 0; k < 128; k++) {
            float4 w = *reinterpret_cast<const float4*>(Ws + k * 32 + cg * 4);
            float x0 = Xs[r0 * 128 + ((k + sh0) & 127)];
            float x1 = Xs[r1 * 128 + ((k + sh1) & 127)];
            a0.x += x0 * w.x; a0.y += x0 * w.y; a0.z += x0 * w.z; a0.w += x0 * w.w;
            a1.x += x1 * w.x; a1.y += x1 * w.y; a1.z += x1 * w.z; a1.w += x1 * w.w;
        }
        int gr0 = row0 + r0;
        if (gr0 < N_NODES) *reinterpret_cast<float4*>(Y + gr0 * MOUT + ct + cg * 4) = a0;
        int gr1 = row0 + r1;
        if (gr1 < N_NODES) *reinterpret_cast<float4*>(Y + gr1 * MOUT + ct + cg * 4) = a1;
        __syncthreads();
    }
}

// ---------------- fused GAT layer 1: softmax(no-max) + weighted sum + ELU ----------------
// warp per node; lane owns 4 dims (head = lane/4, 16 dims per head = 4 lanes)
__device__ __forceinline__ float eluf(float x) {
    return x > 0.f ? x : expm1f(x);
}

__global__ __launch_bounds__(256) void k_gat1() {
    int w = (blockIdx.x * blockDim.x + threadIdx.x) >> 5;
    if (w >= N_NODES) return;
    int lane = threadIdx.x & 31;

    const float* fp = g_feat1;
    float4 fd = *reinterpret_cast<const float4*>(fp + w * 128 + lane * 4);
    float a0 = 0.f, a1 = 0.f, a2 = 0.f, a3 = 0.f, den = 0.f;

    int i = g_rs[w], end = g_rs[w + 1];
    for (; i + 1 < end; i += 2) {
        int s0 = g_col[i], s1 = g_col[i + 1];
        float4 f0 = *reinterpret_cast<const float4*>(fp + s0 * 128 + lane * 4);
        float4 f1 = *reinterpret_cast<const float4*>(fp + s1 * 128 + lane * 4);
        float p0 = f0.x * fd.x + f0.y * fd.y + f0.z * fd.z + f0.w * fd.w;
        float p1 = f1.x * fd.x + f1.y * fd.y + f1.z * fd.z + f1.w * fd.w;
        p0 += __shfl_xor_sync(0xffffffffu, p0, 1);
        p0 += __shfl_xor_sync(0xffffffffu, p0, 2);
        p1 += __shfl_xor_sync(0xffffffffu, p1, 1);
        p1 += __shfl_xor_sync(0xffffffffu, p1, 2);
        float e0 = __expf(p0 * 0.25f);   // scale = HIDDEN^-0.5 = 0.25
        float e1 = __expf(p1 * 0.25f);
        den += e0 + e1;
        a0 += e0 * f0.x + e1 * f1.x;
        a1 += e0 * f0.y + e1 * f1.y;
        a2 += e0 * f0.z + e1 * f1.z;
        a3 += e0 * f0.w + e1 * f1.w;
    }
    if (i < end) {
        int s0 = g_col[i];
        float4 f0 = *reinterpret_cast<const float4*>(fp + s0 * 128 + lane * 4);
        float p0 = f0.x * fd.x + f0.y * fd.y + f0.z * fd.z + f0.w * fd.w;
        p0 += __shfl_xor_sync(0xffffffffu, p0, 1);
        p0 += __shfl_xor_sync(0xffffffffu, p0, 2);
        float e0 = __expf(p0 * 0.25f);
        den += e0;
        a0 += e0 * f0.x; a1 += e0 * f0.y; a2 += e0 * f0.z; a3 += e0 * f0.w;
    }

    float inv = 1.f / fmaxf(den, 1e-9f);
    float4 o;
    o.x = eluf(a0 * inv);
    o.y = eluf(a1 * inv);
    o.z = eluf(a2 * inv);
    o.w = eluf(a3 * inv);
    *reinterpret_cast<float4*>(g_h1 + w * 128 + lane * 4) = o;
}

// ---------------- fused GAT layer 2: single head, D=64, lane owns 2 dims ----------------
__global__ __launch_bounds__(256) void k_gat2(float* __restrict__ out) {
    int w = (blockIdx.x * blockDim.x + threadIdx.x) >> 5;
    if (w >= N_NODES) return;
    int lane = threadIdx.x & 31;

    const float* fp = g_feat2;
    float2 fd = *reinterpret_cast<const float2*>(fp + w * 64 + lane * 2);
    float a0 = 0.f, a1 = 0.f, den = 0.f;

    int i = g_rs[w], end = g_rs[w + 1];
    for (; i + 1 < end; i += 2) {
        int s0 = g_col[i], s1 = g_col[i + 1];
        float2 f0 = *reinterpret_cast<const float2*>(fp + s0 * 64 + lane * 2);
        float2 f1 = *reinterpret_cast<const float2*>(fp + s1 * 64 + lane * 2);
        float p0 = f0.x * fd.x + f0.y * fd.y;
        float p1 = f1.x * fd.x + f1.y * fd.y;
#pragma unroll
        for (int off = 16; off; off >>= 1) {
            p0 += __shfl_xor_sync(0xffffffffu, p0, off);
            p1 += __shfl_xor_sync(0xffffffffu, p1, off);
        }
        float e0 = __expf(p0 * 0.125f);  // scale = 64^-0.5
        float e1 = __expf(p1 * 0.125f);
        den += e0 + e1;
        a0 += e0 * f0.x + e1 * f1.x;
        a1 += e0 * f0.y + e1 * f1.y;
    }
    if (i < end) {
        int s0 = g_col[i];
        float2 f0 = *reinterpret_cast<const float2*>(fp + s0 * 64 + lane * 2);
        float p0 = f0.x * fd.x + f0.y * fd.y;
#pragma unroll
        for (int off = 16; off; off >>= 1)
            p0 += __shfl_xor_sync(0xffffffffu, p0, off);
        float e0 = __expf(p0 * 0.125f);
        den += e0;
        a0 += e0 * f0.x;
        a1 += e0 * f0.y;
    }

    float inv = 1.f / fmaxf(den, 1e-9f);
    *reinterpret_cast<float2*>(out + w * 64 + lane * 2) = make_float2(a0 * inv, a1 * inv);
}

// ---------------- launch ----------------
extern "C" void kernel_launch(void* const* d_in, const int* in_sizes, int n_in,
                              void* d_out, int out_size) {
    const float* h   = (const float*)d_in[0];
    const float* W1  = (const float*)d_in[1];
    const float* W2  = (const float*)d_in[2];
    const int*   src = (const int*)d_in[3];
    const int*   dst = (const int*)d_in[4];
    float*       out = (float*)d_out;

    // device addresses of __device__ scratch (pure lookup, capture-safe)
    float *p_feat1 = nullptr, *p_h1 = nullptr, *p_feat2 = nullptr;
    cudaGetSymbolAddress((void**)&p_feat1, g_feat1);
    cudaGetSymbolAddress((void**)&p_h1, g_h1);
    cudaGetSymbolAddress((void**)&p_feat2, g_feat2);

    const int TB = 256;
    k_reset<<<(N_NODES + TB - 1) / TB, TB>>>();
    k_hist<<<(N_EDGES + TB - 1) / TB, TB>>>(dst);
    k_scan<<<1, 1024>>>();
    k_fill<<<(N_EDGES + TB - 1) / TB, TB>>>(src, dst);

    k_gemm<128><<<(N_NODES + 63) / 64, 256>>>(h, W1, p_feat1);   // feat1 = h @ W1
    k_gat1<<<(N_NODES * 32 + TB - 1) / TB, TB>>>();              // h1 = elu(gat(feat1))
    k_gemm<64><<<(N_NODES + 63) / 64, 256>>>(p_h1, W2, p_feat2); // feat2 = h1 @ W2
    k_gat2<<<(N_NODES * 32 + TB - 1) / TB, TB>>>(out);           // out = gat(feat2)
}